// round 8
// baseline (speedup 1.0000x reference)
#include <cuda_runtime.h>
#include <cuda_fp16.h>
#include <math.h>
#include <stdint.h>

#define D_DIM 128
#define K_DIM 512
#define TMROWS 64
#define NTHREADS 256
#define SOFTMIN_BETA 10.0f

#define DSTRIDE 516                 // s_dist row stride (floats)
#define LHSTR 66                    // s_latH row stride (half2 units)
#define ESTRB 272                   // s_embT d-row stride (bytes)
#define EBUF 34816                  // 128 * ESTRB per buffer
#define OFF_LATH 132096
#define OFF_EMB  148992
#define OFF_ESQ  218624
#define OFF_ROWSQ 220672
#define SMEM_BYTES 220928

// ---------------- device globals (zero at load; self-reset each call) ----------------
__device__ double g_sq_sum;
__device__ double g_mind_sum;
__device__ unsigned int g_counts[K_DIM];
__device__ unsigned int g_done;

// ---------------- single fused kernel ----------------
__global__ void __launch_bounds__(NTHREADS) vq_main_kernel(
    const float* __restrict__ latents,
    const float* __restrict__ emb,
    float* __restrict__ out_q,
    float* __restrict__ out_ind,
    float* __restrict__ out_soft,
    float* __restrict__ out_vq,
    float* __restrict__ out_ent,
    float* __restrict__ out_cm)
{
    extern __shared__ __align__(16) unsigned char smem[];
    float*   s_dist  = (float*)smem;                          // 64 x DSTRIDE
    __half2* s_latH  = (__half2*)(smem + OFF_LATH);           // 64 x LHSTR
    float*   s_esq   = (float*)(smem + OFF_ESQ);              // 512 approx (softmax only)
    float*   s_rowsq = (float*)(smem + OFF_ROWSQ);            // 64 exact chains

    const int tid = threadIdx.x;
    const int wid = tid >> 5, tx = tid & 31;
    const long long row0 = (long long)blockIdx.x * TMROWS;

    // --- stage latents as fp16 pairs (d, d+1) ---
    {
        const float4* lat4 = (const float4*)(latents + row0 * D_DIM);
#pragma unroll
        for (int it = 0; it < 8; ++it) {
            int u = it * NTHREADS + tid;
            int row = u >> 5, c4 = u & 31;
            float4 x = lat4[u];
            __half2* dst = s_latH + row * LHSTR + c4 * 2;
            dst[0] = __floats2half2_rn(x.x, x.y);
            dst[1] = __floats2half2_rn(x.z, x.w);
        }
    }
    // --- approx emb row norms (softmax only) ---
    for (int kk = tid; kk < K_DIM; kk += NTHREADS) {
        const float4* e4 = (const float4*)(emb + (size_t)kk * D_DIM);
        float s = 0.f;
#pragma unroll
        for (int i = 0; i < 32; ++i) {
            float4 v = e4[i];
            s += v.x * v.x + v.y * v.y + v.z * v.z + v.w * v.w;
        }
        s_esq[kk] = s;
    }
    // --- rowsq: exact sequential reference chains ---
    if (tid < TMROWS) {
        const float* lr = latents + (row0 + tid) * D_DIM;
        float s = 0.f;
        for (int d = 0; d < D_DIM; ++d)
            s = __fadd_rn(s, __fmul_rn(lr[d], lr[d]));
        s_rowsq[tid] = s;
    }

    // --- emb quarter fill: fp16 scaled x256, transposed [d][k] ---
    const int kr = tid >> 1, dh = (tid & 1) * 64;
    auto fill = [&](int buf, int q) {
        const float4* src = (const float4*)(emb + (size_t)(q * 128 + kr) * D_DIM + dh);
        unsigned char* sb = smem + OFF_EMB + buf * EBUF;
#pragma unroll
        for (int j = 0; j < 16; ++j) {
            float4 v = src[j];
            int d = dh + j * 4;
            unsigned char* c = sb + kr * 2;
            *(__half*)(c + (d + 0) * ESTRB) = __float2half_rn(v.x * 256.f);
            *(__half*)(c + (d + 1) * ESTRB) = __float2half_rn(v.y * 256.f);
            *(__half*)(c + (d + 2) * ESTRB) = __float2half_rn(v.z * 256.f);
            *(__half*)(c + (d + 3) * ESTRB) = __float2half_rn(v.w * 256.f);
        }
    };

    fill(0, 0);
    __syncthreads();

    // ---- GEMM: 4 k-quarters, HFMA2 dual-MAC, fp32 promote every 32 d ----
    const __half2* aR = s_latH + (wid * 8) * LHSTR;
    for (int q = 0; q < 4; ++q) {
        if (q < 3) fill((q + 1) & 1, q + 1);
        const unsigned char* sb = smem + OFF_EMB + (q & 1) * EBUF;

        float2 accF[8][2];
        __half2 accH[8][2];
#pragma unroll
        for (int i = 0; i < 8; ++i)
#pragma unroll
            for (int p = 0; p < 2; ++p) {
                accF[i][p] = make_float2(0.f, 0.f);
                accH[i][p] = __floats2half2_rn(0.f, 0.f);
            }

#pragma unroll 8
        for (int d2 = 0; d2 < 64; ++d2) {
            __half2 av[8], bv0[2], bv1[2];
#pragma unroll
            for (int i = 0; i < 8; ++i) av[i] = aR[i * LHSTR + d2];   // warp-broadcast
#pragma unroll
            for (int p = 0; p < 2; ++p) {
                bv0[p] = *(const __half2*)(sb + (2 * d2) * ESTRB + 4 * tx + 128 * p);
                bv1[p] = *(const __half2*)(sb + (2 * d2 + 1) * ESTRB + 4 * tx + 128 * p);
            }
#pragma unroll
            for (int i = 0; i < 8; ++i) {
                __half2 alo = __low2half2(av[i]);
                __half2 ahi = __high2half2(av[i]);
                accH[i][0] = __hfma2(alo, bv0[0], accH[i][0]);
                accH[i][0] = __hfma2(ahi, bv1[0], accH[i][0]);
                accH[i][1] = __hfma2(alo, bv0[1], accH[i][1]);
                accH[i][1] = __hfma2(ahi, bv1[1], accH[i][1]);
            }
            if ((d2 & 15) == 15) {   // promote to fp32 every 32 d
#pragma unroll
                for (int i = 0; i < 8; ++i)
#pragma unroll
                    for (int p = 0; p < 2; ++p) {
                        float2 f = __half22float2(accH[i][p]);
                        accF[i][p].x += f.x;
                        accF[i][p].y += f.y;
                        accH[i][p] = __floats2half2_rn(0.f, 0.f);
                    }
            }
        }

        // dist = fl( fl(rowsq+esq) - dotScaled/128 )   (dot was scaled by 256)
#pragma unroll
        for (int i = 0; i < 8; ++i) {
            int r = wid * 8 + i;
            float rs = s_rowsq[r];
#pragma unroll
            for (int p = 0; p < 2; ++p) {
                int k = q * 128 + 2 * tx + 64 * p;
                float2 es = *(const float2*)(s_esq + k);
                float2 dv2;
                dv2.x = __fmaf_rn(accF[i][p].x, -0.0078125f, __fadd_rn(rs, es.x));
                dv2.y = __fmaf_rn(accF[i][p].y, -0.0078125f, __fadd_rn(rs, es.y));
                *(float2*)(s_dist + r * DSTRIDE + k) = dv2;
            }
        }
        __syncthreads();
    }

    // ---- epilogue: approx-min -> exact rescue (reference grid) -> softmax -> outputs ----
    float warp_sq = 0.f, warp_cm = 0.f;
    const int lane = tx;

#pragma unroll 1
    for (int i = 0; i < 8; ++i) {
        int r = wid * 8 + i;
        const float* dr = s_dist + r * DSTRIDE;

        float dv[16];
        float bv = 3.4e38f;
#pragma unroll
        for (int t = 0; t < 16; ++t) {
            float x = dr[lane + 32 * t];
            dv[t] = x;
            bv = fminf(bv, x);
        }
#pragma unroll
        for (int o = 16; o; o >>= 1)
            bv = fminf(bv, __shfl_xor_sync(0xffffffffu, bv, o));

        // exact rescue: sequential reference chains for dot and ||e||^2
        const float margin = 4e-4f;
        const float rsq = s_rowsq[r];
        const float* lrow = latents + (row0 + r) * D_DIM;
        float bestd = 3.4e38f;
        int bestk = 0x7fffffff;
#pragma unroll 1
        for (int t = 0; t < 16; ++t) {
            if (dv[t] <= bv + margin) {
                int k = lane + 32 * t;
                const float* er = emb + (size_t)k * D_DIM;
                float a = 0.f, qq = 0.f;
                for (int d = 0; d < D_DIM; ++d) {
                    float ev = er[d];
                    a = __fmaf_rn(lrow[d], ev, a);
                    qq = __fadd_rn(qq, __fmul_rn(ev, ev));
                }
                float de = __fmaf_rn(-2.f, a, __fadd_rn(rsq, qq));
                if (de < bestd || (de == bestd && k < bestk)) { bestd = de; bestk = k; }
            }
        }
#pragma unroll
        for (int o = 16; o; o >>= 1) {
            float od = __shfl_xor_sync(0xffffffffu, bestd, o);
            int   ok = __shfl_xor_sync(0xffffffffu, bestk, o);
            if (od < bestd || (od == bestd && ok < bestk)) { bestd = od; bestk = ok; }
        }

        long long rg = row0 + r;
        if (lane == 0) {
            atomicAdd(&g_counts[bestk], 1u);
            out_ind[rg] = (float)bestk;
            warp_cm += bestd;
        }

        float ev[16], sum = 0.f;
#pragma unroll
        for (int t = 0; t < 16; ++t) {
            float e = __expf(-SOFTMIN_BETA * (dv[t] - bv));
            ev[t] = e;
            sum += e;
        }
#pragma unroll
        for (int o = 16; o; o >>= 1) sum += __shfl_xor_sync(0xffffffffu, sum, o);
        float inv = 1.0f / sum;
        float* os = out_soft + rg * K_DIM;
#pragma unroll
        for (int t = 0; t < 16; ++t) os[lane + 32 * t] = ev[t] * inv;

        float4 qv = ((const float4*)emb)[bestk * 32 + lane];
        float4 lv = ((const float4*)(latents + rg * D_DIM))[lane];
        ((float4*)(out_q + rg * D_DIM))[lane] = qv;
        float dx = qv.x - lv.x, dy = qv.y - lv.y, dz = qv.z - lv.z, dw = qv.w - lv.w;
        float sq = dx * dx + dy * dy + dz * dz + dw * dw;
#pragma unroll
        for (int o = 16; o; o >>= 1) sq += __shfl_xor_sync(0xffffffffu, sq, o);
        if (lane == 0) warp_sq += sq;
    }

    if (lane == 0) {
        atomicAdd(&g_sq_sum, (double)warp_sq);
        atomicAdd(&g_mind_sum, (double)warp_cm);
    }

    // ---- last-block finalize: scalars + reset globals (graph-safe, deterministic) ----
    __shared__ int s_last;
    __threadfence();
    __syncthreads();
    if (tid == 0) {
        unsigned int t = atomicAdd(&g_done, 1u);
        s_last = (t == gridDim.x - 1u) ? 1 : 0;
    }
    __syncthreads();
    if (s_last) {
        __threadfence();
        float* red = (float*)smem;   // reuse dist space
        double Bd = (double)gridDim.x * TMROWS;
        float Bf = (float)Bd;
        float p0 = (float)g_counts[tid] / Bf;
        float p1 = (float)g_counts[tid + 256] / Bf;
        red[tid] = -p0 * logf(p0 + 1e-10f) - p1 * logf(p1 + 1e-10f);
        g_counts[tid] = 0u;
        g_counts[tid + 256] = 0u;
        __syncthreads();
        for (int s = 128; s > 0; s >>= 1) {
            if (tid < s) red[tid] += red[tid + s];
            __syncthreads();
        }
        if (tid == 0) {
            out_vq[0]  = (float)((g_sq_sum / (Bd * (double)D_DIM)) * 1.25);
            out_ent[0] = red[0];
            out_cm[0]  = (float)(g_mind_sum / Bd);
            g_sq_sum = 0.0;
            g_mind_sum = 0.0;
            g_done = 0u;
        }
    }
}

extern "C" void kernel_launch(void* const* d_in, const int* in_sizes, int n_in,
                              void* d_out, int out_size)
{
    const float* latents = (const float*)d_in[0];
    const float* emb     = (const float*)d_in[1];
    long long B = (long long)in_sizes[0] / D_DIM;

    float* out      = (float*)d_out;
    float* out_q    = out;
    float* out_vq   = out + B * D_DIM;
    float* out_ent  = out_vq + 1;
    float* out_ind  = out_ent + 1;
    float* out_soft = out_ind + B;
    float* out_cm   = out_soft + B * K_DIM;

    cudaFuncSetAttribute(vq_main_kernel, cudaFuncAttributeMaxDynamicSharedMemorySize, SMEM_BYTES);

    vq_main_kernel<<<(unsigned)(B / TMROWS), NTHREADS, SMEM_BYTES>>>(
        latents, emb, out_q, out_ind, out_soft, out_vq, out_ent, out_cm);
}

// round 9
// speedup vs baseline: 1.6739x; 1.6739x over previous
#include <cuda_runtime.h>
#include <cuda_fp16.h>
#include <math.h>
#include <stdint.h>

#define D_DIM 128
#define K_DIM 512
#define TM 32
#define NTHREADS 256
#define BETA_SM 10.0f

// smem byte offsets
#define USTR 516
#define OFF_U 0                      // 32 x 516 x 4 = 66048
#define OFF_LATH 66048               // 32 x 64 half2 = 8192
#define OFF_EMB  74240               // 128 x 268 = 34304
#define ESTR 268
#define OFF_ESQ  108544              // 512 x 4 = 2048
#define OFF_ROWSQ 110592             // 32 x 4 = 128
#define SMEM_BYTES 110720

// ---------------- device globals (zero at load; self-reset each call) ----------------
__device__ double g_sq_sum;
__device__ double g_mind_sum;
__device__ unsigned int g_counts[K_DIM];
__device__ unsigned int g_done;

// ---------------- single fused kernel ----------------
__global__ void __launch_bounds__(NTHREADS, 2) vq_kernel(
    const float* __restrict__ latents,
    const float* __restrict__ emb,
    float* __restrict__ out_q,
    float* __restrict__ out_ind,
    float* __restrict__ out_soft,
    float* __restrict__ out_vq,
    float* __restrict__ out_ent,
    float* __restrict__ out_cm)
{
    extern __shared__ __align__(16) unsigned char smem[];
    float*   s_u     = (float*)smem;                       // 32 x USTR
    __half2* s_lath  = (__half2*)(smem + OFF_LATH);        // 32 x 64
    float*   s_esq   = (float*)(smem + OFF_ESQ);           // 512 (approx)
    float*   s_rowsq = (float*)(smem + OFF_ROWSQ);         // 32 (exact chains)

    const int tid = threadIdx.x;
    const int wid = tid >> 5, tx = tid & 31;
    const long long row0 = (long long)blockIdx.x * TM;

    // --- stage latents as fp16 (d,d+1) pairs ---
    {
        const float4* lat4 = (const float4*)(latents + row0 * D_DIM);
#pragma unroll
        for (int it = 0; it < 4; ++it) {
            int idx = it * NTHREADS + tid;      // 1024 float4
            int row = idx >> 5, c4 = idx & 31;
            float4 x = lat4[idx];
            s_lath[row * 64 + c4 * 2]     = __floats2half2_rn(x.x, x.y);
            s_lath[row * 64 + c4 * 2 + 1] = __floats2half2_rn(x.z, x.w);
        }
    }
    // --- rowsq: exact sequential reference chain (rescue/cm only) ---
    if (tid < TM) {
        const float* lr = latents + (row0 + tid) * D_DIM;
        float s = 0.f;
        for (int d = 0; d < D_DIM; ++d)
            s = __fadd_rn(s, __fmul_rn(lr[d], lr[d]));
        s_rowsq[tid] = s;
    }

    const int r0 = wid * 4;
    float usum[4] = {0.f, 0.f, 0.f, 0.f};
    float umax[4] = {0.f, 0.f, 0.f, 0.f};
    const __half2 hz = __float2half2_rn(0.f);

    // ---- 4 k-quarters: fill emb fp16 (x256), HFMA2 pairwise-dot GEMM, u = exp ----
    for (int q = 0; q < 4; ++q) {
        __syncthreads();   // previous quarter's reads done
        {
            // fill: thread -> k row (tid>>1), parity-interleaved d4 groups
            int k = tid >> 1, p = tid & 1;
            const float4* src = (const float4*)emb + (size_t)(q * 128 + k) * 32;
            float esq_part = 0.f;
#pragma unroll
            for (int jj = 0; jj < 16; ++jj) {
                float4 v = src[p + 2 * jj];
                esq_part += v.x * v.x + v.y * v.y + v.z * v.z + v.w * v.w;
                int d = p * 4 + 8 * jj;
                __half2* dst = (__half2*)(smem + OFF_EMB + k * ESTR + d * 2);
                dst[0] = __floats2half2_rn(v.x * 256.f, v.y * 256.f);
                dst[1] = __floats2half2_rn(v.z * 256.f, v.w * 256.f);
            }
            esq_part += __shfl_xor_sync(0xffffffffu, esq_part, 1);
            if (p == 0) s_esq[q * 128 + k] = esq_part;
        }
        __syncthreads();

        float accF[4][4];
        __half2 accH[4][4];
#pragma unroll
        for (int i = 0; i < 4; ++i)
#pragma unroll
            for (int j = 0; j < 4; ++j) { accF[i][j] = 0.f; accH[i][j] = hz; }

#pragma unroll 1
        for (int dblk = 0; dblk < 4; ++dblk) {
#pragma unroll
            for (int d2i = 0; d2i < 16; ++d2i) {
                int d2 = dblk * 16 + d2i;
                __half2 av[4], bv[4];
#pragma unroll
                for (int i = 0; i < 4; ++i)
                    av[i] = s_lath[(r0 + i) * 64 + d2];            // broadcast
#pragma unroll
                for (int j = 0; j < 4; ++j)
                    bv[j] = *(const __half2*)(smem + OFF_EMB + (tx + 32 * j) * ESTR + d2 * 4);
#pragma unroll
                for (int i = 0; i < 4; ++i)
#pragma unroll
                    for (int j = 0; j < 4; ++j)
                        accH[i][j] = __hfma2(av[i], bv[j], accH[i][j]);
            }
            // promote to fp32 every 32 d
#pragma unroll
            for (int i = 0; i < 4; ++i)
#pragma unroll
                for (int j = 0; j < 4; ++j) {
                    float2 f = __half22float2(accH[i][j]);
                    accF[i][j] += f.x + f.y;
                    accH[i][j] = hz;
                }
        }

        // u = exp(-10 * (esq - dotS/128)); track sum/max per row
#pragma unroll
        for (int j = 0; j < 4; ++j) {
            int k = q * 128 + tx + 32 * j;
            float es = s_esq[k];
#pragma unroll
            for (int i = 0; i < 4; ++i) {
                float dsh = __fmaf_rn(accF[i][j], -0.0078125f, es);
                float u = __expf(-BETA_SM * dsh);
                s_u[(r0 + i) * USTR + k] = u;
                usum[i] += u;
                umax[i] = fmaxf(umax[i], u);
            }
        }
    }

    // ---- warp-reduce per-row sum/max (all lanes get result) ----
#pragma unroll
    for (int i = 0; i < 4; ++i)
#pragma unroll
        for (int o = 16; o; o >>= 1) {
            usum[i] += __shfl_xor_sync(0xffffffffu, usum[i], o);
            umax[i] = fmaxf(umax[i], __shfl_xor_sync(0xffffffffu, umax[i], o));
        }

    // ---- phase 2: probs, exact-rescue argmin, outputs (warp owns its 4 rows) ----
    float warp_sq = 0.f, warp_cm = 0.f;

#pragma unroll 1
    for (int i = 0; i < 4; ++i) {
        int r = r0 + i;
        long long rg = row0 + r;
        const float* ur = s_u + r * USTR;
        float inv = 1.0f / usum[i];
        float thr = umax[i] * 0.9955f;      // == dist margin ~4.5e-4 (round-8 validated)

        // coalesced prob writes
        float* os = out_soft + rg * K_DIM;
#pragma unroll
        for (int t = 0; t < 16; ++t)
            os[tx + 32 * t] = ur[tx + 32 * t] * inv;

        // candidates -> exact sequential-chain recompute on the reference grid
        const float rsq = s_rowsq[r];
        const float* lrow = latents + rg * D_DIM;
        float bestd = 3.4e38f;
        int bestk = 0x7fffffff;
#pragma unroll 1
        for (int t = 0; t < 16; ++t) {
            if (ur[tx + 32 * t] >= thr) {
                int k = tx + 32 * t;
                const float* er = emb + (size_t)k * D_DIM;
                float a = 0.f, qq = 0.f;
                for (int d = 0; d < D_DIM; ++d) {
                    float ev = er[d];
                    a = __fmaf_rn(lrow[d], ev, a);
                    qq = __fadd_rn(qq, __fmul_rn(ev, ev));
                }
                float de = __fmaf_rn(-2.f, a, __fadd_rn(rsq, qq));
                if (de < bestd || (de == bestd && k < bestk)) { bestd = de; bestk = k; }
            }
        }
#pragma unroll
        for (int o = 16; o; o >>= 1) {
            float od = __shfl_xor_sync(0xffffffffu, bestd, o);
            int   ok = __shfl_xor_sync(0xffffffffu, bestk, o);
            if (od < bestd || (od == bestd && ok < bestk)) { bestd = od; bestk = ok; }
        }

        if (tx == 0) {
            atomicAdd(&g_counts[bestk], 1u);
            out_ind[rg] = (float)bestk;
            warp_cm += bestd;
        }

        // quantized output + vq loss accumulation
        float4 qv = ((const float4*)emb)[bestk * 32 + tx];
        float4 lv = ((const float4*)lrow)[tx];
        ((float4*)(out_q + rg * D_DIM))[tx] = qv;
        float dx = qv.x - lv.x, dy = qv.y - lv.y, dz = qv.z - lv.z, dw = qv.w - lv.w;
        float sq = dx * dx + dy * dy + dz * dz + dw * dw;
#pragma unroll
        for (int o = 16; o; o >>= 1) sq += __shfl_xor_sync(0xffffffffu, sq, o);
        if (tx == 0) warp_sq += sq;
    }

    if (tx == 0) {
        atomicAdd(&g_sq_sum, (double)warp_sq);
        atomicAdd(&g_mind_sum, (double)warp_cm);
    }

    // ---- last-block finalize: scalars + reset globals ----
    __shared__ int s_last;
    __threadfence();
    __syncthreads();
    if (tid == 0) {
        unsigned int t = atomicAdd(&g_done, 1u);
        s_last = (t == gridDim.x - 1u) ? 1 : 0;
    }
    __syncthreads();
    if (s_last) {
        __threadfence();
        float* red = s_u;   // reuse
        double Bd = (double)gridDim.x * TM;
        float Bf = (float)Bd;
        float p0 = (float)g_counts[tid] / Bf;
        float p1 = (float)g_counts[tid + 256] / Bf;
        red[tid] = -p0 * logf(p0 + 1e-10f) - p1 * logf(p1 + 1e-10f);
        g_counts[tid] = 0u;
        g_counts[tid + 256] = 0u;
        __syncthreads();
        for (int s = 128; s > 0; s >>= 1) {
            if (tid < s) red[tid] += red[tid + s];
            __syncthreads();
        }
        if (tid == 0) {
            out_vq[0]  = (float)((g_sq_sum / (Bd * (double)D_DIM)) * 1.25);
            out_ent[0] = red[0];
            out_cm[0]  = (float)(g_mind_sum / Bd);
            g_sq_sum = 0.0;
            g_mind_sum = 0.0;
            g_done = 0u;
        }
    }
}

extern "C" void kernel_launch(void* const* d_in, const int* in_sizes, int n_in,
                              void* d_out, int out_size)
{
    const float* latents = (const float*)d_in[0];
    const float* emb     = (const float*)d_in[1];
    long long B = (long long)in_sizes[0] / D_DIM;

    float* out      = (float*)d_out;
    float* out_q    = out;
    float* out_vq   = out + B * D_DIM;
    float* out_ent  = out_vq + 1;
    float* out_ind  = out_ent + 1;
    float* out_soft = out_ind + B;
    float* out_cm   = out_soft + B * K_DIM;

    cudaFuncSetAttribute(vq_kernel, cudaFuncAttributeMaxDynamicSharedMemorySize, SMEM_BYTES);

    vq_kernel<<<(unsigned)(B / TM), NTHREADS, SMEM_BYTES>>>(
        latents, emb, out_q, out_ind, out_soft, out_vq, out_ent, out_cm);
}